// round 2
// baseline (speedup 1.0000x reference)
#include <cuda_runtime.h>

// Problem constants
static constexpr int B_  = 4;
static constexpr int H_  = 64;
static constexpr int W_  = 64;
static constexpr int C_  = 256;   // concat channels
static constexpr int HW_ = H_ * W_;          // 4096
static constexpr int M_  = B_ * HW_;         // 16384 pixels
static constexpr int K9  = 9;

// ---------------- scratch (device globals; no allocation allowed) ----------
__device__ float  g_feat0[(size_t)M_ * C_];          // 16 MB  NHWC
__device__ float  g_feat1[(size_t)M_ * C_];          // 16 MB  NHWC
__device__ float  g_wOt[4 * 9 * C_ * 32];            // offset weights [i][tap][c][o(pad32)]
__device__ float  g_wDt[3 * 9 * C_ * C_];            // deform weights [i][tap][c][o]
__device__ float  g_offraw[(size_t)M_ * 32];         // raw offset-conv output [m][n]
__device__ int4   g_recIdx[(size_t)M_ * 9];          // 4 clamped corner base indices (in floats)
__device__ float4 g_recW[(size_t)M_ * 9];            // 4 validity-folded bilinear weights

// ---------------- pack: NCHW x,y -> NHWC concat feat0 ----------------------
__global__ void pack_kernel(const float* __restrict__ x, const float* __restrict__ y)
{
    __shared__ float t[32][33];
    int b   = blockIdx.z;
    int hw0 = blockIdx.x * 32;
    int c0  = blockIdx.y * 32;
    int tx  = threadIdx.x, ty = threadIdx.y;   // block (32,8)

#pragma unroll
    for (int i = 0; i < 32; i += 8) {
        int c = c0 + ty + i;
        const float* s = (c < 128) ? (x + ((size_t)b * 128 + c)       * HW_)
                                   : (y + ((size_t)b * 128 + (c-128)) * HW_);
        t[ty + i][tx] = s[hw0 + tx];
    }
    __syncthreads();
#pragma unroll
    for (int i = 0; i < 32; i += 8) {
        int hw = hw0 + ty + i;
        g_feat0[((size_t)b * HW_ + hw) * C_ + c0 + tx] = t[tx][ty + i];
    }
}

// ---------------- weight transpose: [o][c][3][3] -> [tap][c][o] ------------
__global__ void wtrans_kernel(const float* __restrict__ oW, const float* __restrict__ dW)
{
    const int total1 = 4 * 9 * C_ * 32;      // 294912
    const int total2 = 3 * 9 * C_ * C_;      // 1769472
    for (int idx = blockIdx.x * blockDim.x + threadIdx.x;
         idx < total1 + total2; idx += gridDim.x * blockDim.x) {
        if (idx < total1) {
            int o   = idx & 31;
            int c   = (idx >> 5) & 255;
            int tap = (idx >> 13) % 9;
            int i   = (idx >> 13) / 9;
            g_wOt[idx] = (o < 18) ? oW[(((i * 18 + o) * 256 + c) * 9) + tap] : 0.f;
        } else {
            int j   = idx - total1;
            int o   = j & 255;
            int c   = (j >> 8) & 255;
            int tap = (j >> 16) % 9;
            int i   = (j >> 16) / 9;
            g_wDt[j] = dW[(((i * 256 + o) * 256 + c) * 9) + tap];
        }
    }
}

// ---------------- coords: raw offsets -> gather records --------------------
__global__ void coords_kernel()
{
    int idx = blockIdx.x * blockDim.x + threadIdx.x;
    if (idx >= M_ * 9) return;
    int k = idx % 9;
    int m = idx / 9;
    int b = m >> 12;
    int hw = m & 4095;
    int h = hw >> 6, w = hw & 63;

    float dy = g_offraw[(size_t)m * 32 + 2 * k];
    float dx = g_offraw[(size_t)m * 32 + 2 * k + 1];
    float py = dy + (float)(k / 3 - 1) + (float)h;
    float px = dx + (float)(k % 3 - 1) + (float)w;

    float y0f = floorf(py), x0f = floorf(px);
    float wy1 = py - y0f, wy0 = 1.f - wy1;
    float wx1 = px - x0f, wx0 = 1.f - wx1;
    int y0 = (int)y0f, x0 = (int)x0f;
    int y1 = y0 + 1, x1 = x0 + 1;

    int4 ii; float4 ww;
    {
        bool v = (y0 >= 0 && y0 < H_ && x0 >= 0 && x0 < W_);
        int yc = min(max(y0, 0), H_-1), xc = min(max(x0, 0), W_-1);
        ii.x = ((b << 12) + (yc << 6) + xc) << 8;  ww.x = v ? wy0 * wx0 : 0.f;
    }
    {
        bool v = (y0 >= 0 && y0 < H_ && x1 >= 0 && x1 < W_);
        int yc = min(max(y0, 0), H_-1), xc = min(max(x1, 0), W_-1);
        ii.y = ((b << 12) + (yc << 6) + xc) << 8;  ww.y = v ? wy0 * wx1 : 0.f;
    }
    {
        bool v = (y1 >= 0 && y1 < H_ && x0 >= 0 && x0 < W_);
        int yc = min(max(y1, 0), H_-1), xc = min(max(x0, 0), W_-1);
        ii.z = ((b << 12) + (yc << 6) + xc) << 8;  ww.z = v ? wy1 * wx0 : 0.f;
    }
    {
        bool v = (y1 >= 0 && y1 < H_ && x1 >= 0 && x1 < W_);
        int yc = min(max(y1, 0), H_-1), xc = min(max(x1, 0), W_-1);
        ii.w = ((b << 12) + (yc << 6) + xc) << 8;  ww.w = v ? wy1 * wx1 : 0.f;
    }
    g_recIdx[idx] = ii;
    g_recW[idx]   = ww;
}

// ---------------- unified implicit-GEMM conv -------------------------------
// out[m][n] = sum_{tap,c} V[m][tap*C+c] * wT[tap][c][n]
// DEFORM: V via bilinear records. !DEFORM: regular 3x3 taps (zero-pad).
template <int BM, int BN, int TM, int TN, bool DEFORM>
__global__ __launch_bounds__(256, 2)
void gemm_kernel(int fsel, int wsel, float* __restrict__ finalOut)
{
    constexpr int BK  = 16;
    constexpr int CPP = 256 / BM;          // threads per pixel for A-tile
    constexpr int CH  = BK / CPP;          // channels per thread per K-step
    constexpr int NW  = DEFORM ? 256 : 32; // B matrix width

    const float* __restrict__ fin = fsel ? g_feat1 : g_feat0;
    float* __restrict__ fout      = fsel ? g_feat0 : g_feat1;
    const float* __restrict__ wT  = DEFORM ? (g_wDt + (size_t)wsel * 9 * C_ * C_)
                                           : (g_wOt + (size_t)wsel * 9 * C_ * 32);

    __shared__ float  As[BK][BM + 4];
    __shared__ float  Bs[BK][BN];
    __shared__ int4   sIdx[BM];
    __shared__ float4 sW[BM];
    __shared__ int    sBase[BM];

    const int tid = threadIdx.x;
    const int bm0 = blockIdx.y * BM;
    const int bn0 = blockIdx.x * BN;

    const int ty = tid / (BN / TN);
    const int tx = tid % (BN / TN);

    const int p   = tid / CPP;        // pixel within tile
    const int cb  = (tid % CPP) * CH; // channel offset within BK

    float acc[TM][TN];
#pragma unroll
    for (int i = 0; i < TM; i++)
#pragma unroll
        for (int j = 0; j < TN; j++) acc[i][j] = 0.f;

    for (int tap = 0; tap < 9; ++tap) {
        // stage per-pixel sampling metadata for this tap
        if (tid < BM) {
            int m = bm0 + tid;
            if (DEFORM) {
                sIdx[tid] = g_recIdx[(size_t)m * 9 + tap];
                sW[tid]   = g_recW[(size_t)m * 9 + tap];
            } else {
                int b = m >> 12, hw = m & 4095;
                int h = hw >> 6, w = hw & 63;
                int yy = h + tap / 3 - 1, xx = w + tap % 3 - 1;
                sBase[tid] = (yy >= 0 && yy < H_ && xx >= 0 && xx < W_)
                             ? (((b << 12) + (yy << 6) + xx) << 8) : -1;
            }
        }

        for (int cc = 0; cc < C_; cc += BK) {
            __syncthreads();   // staging visible + previous compute done

            // ---- load B tile ----
            const float* wrow = wT + (size_t)(tap * C_ + cc) * NW + bn0;
            for (int q = tid; q < BK * BN / 4; q += 256) {
                int kk = q / (BN / 4);
                int c4 = q % (BN / 4);
                float4 v = *(const float4*)(wrow + (size_t)kk * NW + c4 * 4);
                *(float4*)&Bs[kk][c4 * 4] = v;
            }

            // ---- produce A tile (im2col on the fly) ----
            if (DEFORM) {
                int4   ii  = sIdx[p];
                float4 wwt = sW[p];
#pragma unroll
                for (int j4 = 0; j4 < CH / 4; j4++) {
                    int co = cc + cb + j4 * 4;
                    float4 a = *(const float4*)(fin + ii.x + co);
                    float4 b = *(const float4*)(fin + ii.y + co);
                    float4 c = *(const float4*)(fin + ii.z + co);
                    float4 d = *(const float4*)(fin + ii.w + co);
                    float4 r;
                    r.x = wwt.x * a.x + wwt.y * b.x + wwt.z * c.x + wwt.w * d.x;
                    r.y = wwt.x * a.y + wwt.y * b.y + wwt.z * c.y + wwt.w * d.y;
                    r.z = wwt.x * a.z + wwt.y * b.z + wwt.z * c.z + wwt.w * d.z;
                    r.w = wwt.x * a.w + wwt.y * b.w + wwt.z * c.w + wwt.w * d.w;
                    As[cb + j4 * 4 + 0][p] = r.x;
                    As[cb + j4 * 4 + 1][p] = r.y;
                    As[cb + j4 * 4 + 2][p] = r.z;
                    As[cb + j4 * 4 + 3][p] = r.w;
                }
            } else {
                int base = sBase[p];
#pragma unroll
                for (int j4 = 0; j4 < CH / 4; j4++) {
                    float4 r = make_float4(0.f, 0.f, 0.f, 0.f);
                    if (base >= 0)
                        r = *(const float4*)(fin + base + cc + cb + j4 * 4);
                    As[cb + j4 * 4 + 0][p] = r.x;
                    As[cb + j4 * 4 + 1][p] = r.y;
                    As[cb + j4 * 4 + 2][p] = r.z;
                    As[cb + j4 * 4 + 3][p] = r.w;
                }
            }
            __syncthreads();

            // ---- compute ----
#pragma unroll
            for (int kk = 0; kk < BK; kk++) {
                float ra[TM], rb[TN];
#pragma unroll
                for (int i = 0; i < TM; i++) ra[i] = As[kk][ty * TM + i];
#pragma unroll
                for (int j = 0; j < TN; j++) rb[j] = Bs[kk][tx * TN + j];
#pragma unroll
                for (int i = 0; i < TM; i++)
#pragma unroll
                    for (int j = 0; j < TN; j++)
                        acc[i][j] += ra[i] * rb[j];
            }
        }
    }

    // ---- epilogue ----
    if (DEFORM) {
#pragma unroll
        for (int i = 0; i < TM; i++) {
            int m = bm0 + ty * TM + i;
            float* o = fout + (size_t)m * C_ + bn0 + tx * TN;
#pragma unroll
            for (int j4 = 0; j4 < TN / 4; j4++) {
                float4 v = make_float4(acc[i][j4*4+0], acc[i][j4*4+1],
                                       acc[i][j4*4+2], acc[i][j4*4+3]);
                *(float4*)(o + j4 * 4) = v;
            }
        }
    } else if (finalOut == nullptr) {
#pragma unroll
        for (int i = 0; i < TM; i++) {
            int m = bm0 + ty * TM + i;
#pragma unroll
            for (int j = 0; j < TN; j++)
                g_offraw[(size_t)m * 32 + tx * TN + j] = acc[i][j];
        }
    } else {
#pragma unroll
        for (int i = 0; i < TM; i++) {
            int m  = bm0 + ty * TM + i;
            int b  = m >> 12;
            int hw = m & 4095;
#pragma unroll
            for (int j = 0; j < TN; j++) {
                int n = tx * TN + j;
                if (n < 18)
                    finalOut[((size_t)(b * 18 + n)) * HW_ + hw] = acc[i][j];
            }
        }
    }
}

// ---------------------------------------------------------------------------
extern "C" void kernel_launch(void* const* d_in, const int* in_sizes, int n_in,
                              void* d_out, int out_size)
{
    (void)in_sizes; (void)n_in; (void)out_size;
    const float* x  = (const float*)d_in[0];
    const float* y  = (const float*)d_in[1];
    const float* oW = (const float*)d_in[2];   // [4][18][256][3][3]
    const float* dW = (const float*)d_in[3];   // [3][256][256][3][3]
    float* out = (float*)d_out;                // [4][18][64][64]

    // pack NCHW -> NHWC feat0
    dim3 pb(32, 8), pg(HW_ / 32, C_ / 32, B_);
    pack_kernel<<<pg, pb>>>(x, y);

    // weight transpose
    const int tot = 4 * 9 * C_ * 32 + 3 * 9 * C_ * C_;
    wtrans_kernel<<<(tot + 255) / 256, 256>>>(oW, dW);

    dim3 gOff(1, M_ / 64);      // BN=32 (1 col block), BM=64
    dim3 gDef(C_ / 128, M_ / 128);

    int fsel = 0;
    for (int it = 0; it < 3; ++it) {
        gemm_kernel<64, 32, 4, 2, false><<<gOff, 256>>>(fsel, it, nullptr);
        coords_kernel<<<(M_ * 9 + 255) / 256, 256>>>();
        gemm_kernel<128, 128, 8, 8, true><<<gDef, 256>>>(fsel, it, nullptr);
        fsel ^= 1;
    }
    gemm_kernel<64, 32, 4, 2, false><<<gOff, 256>>>(fsel, 3, out);
}

// round 4
// speedup vs baseline: 2.7319x; 2.7319x over previous
#include <cuda_runtime.h>
#include <cuda_bf16.h>
#include <cstdint>

// Arch-specific feature gate: tcgen05 only exists on sm_103a-targeted passes.
#if defined(__CUDA_ARCH__) && (defined(__CUDA_ARCH_FEAT_SM103_ALL) || defined(__CUDA_ARCH_SPECIFIC__) || defined(__CUDA_ARCH_FAMILY_SPECIFIC__))
#define HAS_TC 1
#else
#define HAS_TC 0
#endif

static constexpr int B_  = 4;
static constexpr int H_  = 64;
static constexpr int W_  = 64;
static constexpr int C_  = 256;
static constexpr int HW_ = H_ * W_;   // 4096
static constexpr int M_  = B_ * HW_;  // 16384

// ---------------- device scratch (no allocation allowed) -------------------
__device__ float  g_feat0[(size_t)M_ * C_];   // 16 MB NHWC fp32
__device__ float  g_feat1[(size_t)M_ * C_];   // 16 MB NHWC fp32
__device__ float  g_offraw[(size_t)M_ * 32];  // offset-conv output [m][32]
__device__ int4   g_recIdx[(size_t)M_ * 9];   // 4 corner base indices (elements)
__device__ float4 g_recW[(size_t)M_ * 9];     // 4 validity-folded bilinear weights
// tensor path: pre-split, pre-swizzled bf16 weight tiles
__device__ __nv_bfloat16 g_wDs[(size_t)3 * 9 * 4 * 2 * 256 * 64];
__device__ __nv_bfloat16 g_wOs[(size_t)4 * 9 * 4 * 2 * 32 * 64];
// fallback path: fp32 transposed weights
__device__ float g_wOt[4 * 9 * C_ * 32];
__device__ float g_wDt[3 * 9 * C_ * C_];

// ---------------- PTX helpers (guarded) -------------------------------------
__device__ __forceinline__ uint32_t smem_u32(const void* p) {
    uint32_t a;
    asm("{ .reg .u64 t; cvta.to.shared.u64 t, %1; cvt.u32.u64 %0, t; }" : "=r"(a) : "l"(p));
    return a;
}
#if HAS_TC
__device__ __forceinline__ void mbar_init(uint32_t a, uint32_t cnt) {
    asm volatile("mbarrier.init.shared.b64 [%0], %1;" :: "r"(a), "r"(cnt) : "memory");
}
__device__ __forceinline__ void mbar_wait(uint32_t a, uint32_t phase) {
    asm volatile(
        "{\n\t.reg .pred P;\n\t"
        "WL_%=:\n\t"
        "mbarrier.try_wait.parity.acquire.cta.shared::cta.b64 P, [%0], %1, 0x989680;\n\t"
        "@P bra.uni WD_%=;\n\t"
        "bra.uni WL_%=;\n\t"
        "WD_%=:\n\t}"
        :: "r"(a), "r"(phase) : "memory");
}
__device__ __forceinline__ void tc_commit(uint32_t mbar) {
    asm volatile(
        "tcgen05.commit.cta_group::1.mbarrier::arrive::one.shared::cluster.b64 [%0];"
        :: "r"(mbar) : "memory");
}
__device__ __forceinline__ void mma_f16_ss(uint32_t d, uint64_t ad, uint64_t bd,
                                           uint32_t idesc, uint32_t en) {
    asm volatile(
        "{\n\t.reg .pred p;\n\t"
        "setp.ne.u32 p, %4, 0;\n\t"
        "tcgen05.mma.cta_group::1.kind::f16 [%0], %1, %2, %3, {%5,%5,%5,%5}, p;\n\t}"
        :: "r"(d), "l"(ad), "l"(bd), "r"(idesc), "r"(en), "r"(0u) : "memory");
}
#define LDTM_X32(r, addr) \
    asm volatile( \
        "tcgen05.ld.sync.aligned.32x32b.x32.b32 " \
        "{%0,%1,%2,%3,%4,%5,%6,%7,%8,%9,%10,%11,%12,%13,%14,%15," \
        "%16,%17,%18,%19,%20,%21,%22,%23,%24,%25,%26,%27,%28,%29,%30,%31}, [%32];" \
        : "=r"((r)[0]),"=r"((r)[1]),"=r"((r)[2]),"=r"((r)[3]), \
          "=r"((r)[4]),"=r"((r)[5]),"=r"((r)[6]),"=r"((r)[7]), \
          "=r"((r)[8]),"=r"((r)[9]),"=r"((r)[10]),"=r"((r)[11]), \
          "=r"((r)[12]),"=r"((r)[13]),"=r"((r)[14]),"=r"((r)[15]), \
          "=r"((r)[16]),"=r"((r)[17]),"=r"((r)[18]),"=r"((r)[19]), \
          "=r"((r)[20]),"=r"((r)[21]),"=r"((r)[22]),"=r"((r)[23]), \
          "=r"((r)[24]),"=r"((r)[25]),"=r"((r)[26]),"=r"((r)[27]), \
          "=r"((r)[28]),"=r"((r)[29]),"=r"((r)[30]),"=r"((r)[31]) \
        : "r"(addr))
#endif

// ---------------- pack: NCHW x,y -> NHWC concat feat0 ----------------------
__global__ void pack_kernel(const float* __restrict__ x, const float* __restrict__ y)
{
    __shared__ float t[32][33];
    int b = blockIdx.z, hw0 = blockIdx.x * 32, c0 = blockIdx.y * 32;
    int tx = threadIdx.x, ty = threadIdx.y;
#pragma unroll
    for (int i = 0; i < 32; i += 8) {
        int c = c0 + ty + i;
        const float* s = (c < 128) ? (x + ((size_t)b * 128 + c) * HW_)
                                   : (y + ((size_t)b * 128 + (c - 128)) * HW_);
        t[ty + i][tx] = s[hw0 + tx];
    }
    __syncthreads();
#pragma unroll
    for (int i = 0; i < 32; i += 8)
        g_feat0[((size_t)b * HW_ + hw0 + ty + i) * C_ + c0 + tx] = t[tx][ty + i];
}

// ---------------- tensor-path weight split + pre-swizzle --------------------
__global__ void wsplit_kernel(const float* __restrict__ oW, const float* __restrict__ dW)
{
#if HAS_TC
    const int GD = 3 * 9 * 4 * 2048;
    const int GO = 4 * 9 * 4 * 256;
    int g = blockIdx.x * blockDim.x + threadIdx.x;
    if (g >= GD + GO) return;
    if (g < GD) {
        int t = g >> 11, o = g & 2047;
        int chunk = t & 3, tap = (t >> 2) % 9, it = (t >> 2) / 9;
        uint32_t boff = (uint32_t)o * 16;
        uint32_t un = boff ^ ((boff >> 3) & 0x70);
        int n = un >> 7, k0 = (un & 127) >> 1;
        uint32_t hp[4], lp[4];
#pragma unroll
        for (int j2 = 0; j2 < 4; j2++) {
            uint32_t hw = 0, lw = 0;
#pragma unroll
            for (int s = 0; s < 2; s++) {
                int k = k0 + j2 * 2 + s;
                float v = dW[((size_t)(it * 256 + n) * 256 + (size_t)(chunk * 64 + k)) * 9 + tap];
                __nv_bfloat16 h = __float2bfloat16_rn(v);
                __nv_bfloat16 l = __float2bfloat16_rn(v - __bfloat162float(h));
                hw |= (uint32_t)__bfloat16_as_ushort(h) << (16 * s);
                lw |= (uint32_t)__bfloat16_as_ushort(l) << (16 * s);
            }
            hp[j2] = hw; lp[j2] = lw;
        }
        char* base = (char*)(g_wDs + (size_t)(((it * 9 + tap) * 4 + chunk) * 2) * 16384);
        *(uint4*)(base + boff)         = make_uint4(hp[0], hp[1], hp[2], hp[3]);
        *(uint4*)(base + 32768 + boff) = make_uint4(lp[0], lp[1], lp[2], lp[3]);
    } else {
        int g2 = g - GD;
        int t = g2 >> 8, o = g2 & 255;
        int chunk = t & 3, tap = (t >> 2) % 9, it = (t >> 2) / 9;
        uint32_t boff = (uint32_t)o * 16;
        uint32_t un = boff ^ ((boff >> 3) & 0x70);
        int n = un >> 7, k0 = (un & 127) >> 1;
        uint32_t hp[4], lp[4];
#pragma unroll
        for (int j2 = 0; j2 < 4; j2++) {
            uint32_t hw = 0, lw = 0;
#pragma unroll
            for (int s = 0; s < 2; s++) {
                int k = k0 + j2 * 2 + s;
                float v = (n < 18)
                    ? oW[((size_t)(it * 18 + n) * 256 + (size_t)(chunk * 64 + k)) * 9 + tap]
                    : 0.f;
                __nv_bfloat16 h = __float2bfloat16_rn(v);
                __nv_bfloat16 l = __float2bfloat16_rn(v - __bfloat162float(h));
                hw |= (uint32_t)__bfloat16_as_ushort(h) << (16 * s);
                lw |= (uint32_t)__bfloat16_as_ushort(l) << (16 * s);
            }
            hp[j2] = hw; lp[j2] = lw;
        }
        char* base = (char*)(g_wOs + (size_t)(((it * 9 + tap) * 4 + chunk) * 2) * 2048);
        *(uint4*)(base + boff)        = make_uint4(hp[0], hp[1], hp[2], hp[3]);
        *(uint4*)(base + 4096 + boff) = make_uint4(lp[0], lp[1], lp[2], lp[3]);
    }
#endif
}

// ---------------- fallback weight transpose ---------------------------------
__global__ void wtrans_kernel(const float* __restrict__ oW, const float* __restrict__ dW)
{
#if !HAS_TC
    const int total1 = 4 * 9 * C_ * 32;
    const int total2 = 3 * 9 * C_ * C_;
    for (int idx = blockIdx.x * blockDim.x + threadIdx.x;
         idx < total1 + total2; idx += gridDim.x * blockDim.x) {
        if (idx < total1) {
            int o = idx & 31, c = (idx >> 5) & 255;
            int tap = (idx >> 13) % 9, i = (idx >> 13) / 9;
            g_wOt[idx] = (o < 18) ? oW[(((i * 18 + o) * 256 + c) * 9) + tap] : 0.f;
        } else {
            int j = idx - total1;
            int o = j & 255, c = (j >> 8) & 255;
            int tap = (j >> 16) % 9, i = (j >> 16) / 9;
            g_wDt[j] = dW[(((i * 256 + o) * 256 + c) * 9) + tap];
        }
    }
#endif
}

// ---------------- coords: raw offsets -> gather records --------------------
__global__ void coords_kernel()
{
    int idx = blockIdx.x * blockDim.x + threadIdx.x;
    if (idx >= M_ * 9) return;
    int k = idx % 9, m = idx / 9;
    int b = m >> 12, hw = m & 4095, h = hw >> 6, w = hw & 63;
    float dy = g_offraw[(size_t)m * 32 + 2 * k];
    float dx = g_offraw[(size_t)m * 32 + 2 * k + 1];
    float py = dy + (float)(k / 3 - 1) + (float)h;
    float px = dx + (float)(k % 3 - 1) + (float)w;
    float y0f = floorf(py), x0f = floorf(px);
    float wy1 = py - y0f, wy0 = 1.f - wy1;
    float wx1 = px - x0f, wx0 = 1.f - wx1;
    int y0 = (int)y0f, x0 = (int)x0f, y1 = y0 + 1, x1 = x0 + 1;
    int4 ii; float4 ww;
    {
        bool v = (y0 >= 0 && y0 < H_ && x0 >= 0 && x0 < W_);
        int yc = min(max(y0,0),H_-1), xc = min(max(x0,0),W_-1);
        ii.x = ((b << 12) + (yc << 6) + xc) << 8;  ww.x = v ? wy0 * wx0 : 0.f;
    }
    {
        bool v = (y0 >= 0 && y0 < H_ && x1 >= 0 && x1 < W_);
        int yc = min(max(y0,0),H_-1), xc = min(max(x1,0),W_-1);
        ii.y = ((b << 12) + (yc << 6) + xc) << 8;  ww.y = v ? wy0 * wx1 : 0.f;
    }
    {
        bool v = (y1 >= 0 && y1 < H_ && x0 >= 0 && x0 < W_);
        int yc = min(max(y1,0),H_-1), xc = min(max(x0,0),W_-1);
        ii.z = ((b << 12) + (yc << 6) + xc) << 8;  ww.z = v ? wy1 * wx0 : 0.f;
    }
    {
        bool v = (y1 >= 0 && y1 < H_ && x1 >= 0 && x1 < W_);
        int yc = min(max(y1,0),H_-1), xc = min(max(x1,0),W_-1);
        ii.w = ((b << 12) + (yc << 6) + xc) << 8;  ww.w = v ? wy1 * wx1 : 0.f;
    }
    g_recIdx[idx] = ii;
    g_recW[idx]   = ww;
}

// ================= tensor-core conv (sm_103a only) ==========================
template <bool DEFORM>
__global__ __launch_bounds__(256)
void conv_kernel(int fsel, int wsel, float* __restrict__ finalOut)
{
#if HAS_TC
    constexpr int NROWS = DEFORM ? 256 : 32;
    constexpr int NB    = NROWS * 128;
    constexpr uint32_t IDESC =
        (1u << 4) | (1u << 7) | (1u << 10) | ((uint32_t)(NROWS / 8) << 17) | (8u << 24);
    constexpr int TMEMC = DEFORM ? 512 : 128;

    extern __shared__ char smem[];
    const uint32_t sb = smem_u32(smem);
    const int TMEMP = 0, MBAR = 16, SIDX = 64, SWT = 64 + 2048;
    const int ABASE = 8192;                 // [8192, 73728): 4 x 16384 A buffers
    const int BBASE = 8192 + 65536;         // 4 x NB B buffers

    const float* __restrict__ fin = fsel ? g_feat1 : g_feat0;
    float* __restrict__ fout      = fsel ? g_feat0 : g_feat1;
    const __nv_bfloat16* __restrict__ wsrc =
        DEFORM ? (g_wDs + (size_t)wsel * 9 * 4 * 2 * 16384)
               : (g_wOs + (size_t)wsel * 9 * 4 * 2 * 2048);

    const int tid = threadIdx.x, wid = tid >> 5, lid = tid & 31;
    const int bm0 = blockIdx.x * 128;

    if (wid == 0) {
        asm volatile("tcgen05.alloc.cta_group::1.sync.aligned.shared::cta.b32 [%0], %1;"
                     :: "r"(sb + TMEMP), "r"((uint32_t)TMEMC) : "memory");
        asm volatile("tcgen05.relinquish_alloc_permit.cta_group::1.sync.aligned;");
    }
    if (tid == 0) { mbar_init(sb + MBAR, 1); mbar_init(sb + MBAR + 8, 1); }
    __syncthreads();
    uint32_t tb;
    asm volatile("ld.shared.b32 %0, [%1];" : "=r"(tb) : "r"(sb + TMEMP));

    int use0 = 0, use1 = 0;
    const int cl4 = (lid & 15) * 4;
    const int ph  = (lid >> 4);

    for (int tap = 0; tap < 9; ++tap) {
        if (tid < 128) {
            int m = bm0 + tid;
            if (DEFORM) {
                ((int4*)(smem + SIDX))[tid]  = g_recIdx[(size_t)m * 9 + tap];
                ((float4*)(smem + SWT))[tid] = g_recW[(size_t)m * 9 + tap];
            } else {
                int b = m >> 12, hw = m & 4095, h = hw >> 6, w = hw & 63;
                int yy = h + tap / 3 - 1, xx = w + tap % 3 - 1;
                ((int*)(smem + SIDX))[tid] =
                    (yy >= 0 && yy < H_ && xx >= 0 && xx < W_)
                        ? (((b << 12) + (yy << 6) + xx) << 8) : -1;
            }
        }
        __syncthreads();

        for (int ch = 0; ch < 4; ++ch) {
            const int ks = tap * 4 + ch;
            const int buf = ks & 1;
            int& u = buf ? use1 : use0;
            if (u > 0) mbar_wait(sb + MBAR + 8 * buf, (u - 1) & 1);

            // B tile copy (pre-swizzled bf16 hi/lo)
            {
                const char* bsh = (const char*)(wsrc + (size_t)(ks * 2) * (NROWS * 64));
                float4* dh = (float4*)(smem + BBASE + (buf * 2 + 0) * NB);
                float4* dl = (float4*)(smem + BBASE + (buf * 2 + 1) * NB);
                const float4* sh = (const float4*)bsh;
                const float4* sl = (const float4*)(bsh + NB);
                for (int q = tid; q < NB / 16; q += 256) { dh[q] = sh[q]; dl[q] = sl[q]; }
            }

            // A tile: gather + bilinear blend + bf16 hi/lo split
            {
                char* ah = smem + ABASE + (buf * 2 + 0) * 16384;
                char* al = smem + ABASE + (buf * 2 + 1) * 16384;
                const int co = ch * 64 + cl4;
#pragma unroll
                for (int pass = 0; pass < 8; ++pass) {
                    int p = pass * 16 + wid * 2 + ph;
                    float4 r;
                    if (DEFORM) {
                        int4   ii = ((const int4*)(smem + SIDX))[p];
                        float4 wt = ((const float4*)(smem + SWT))[p];
                        float4 a = *(const float4*)(fin + ii.x + co);
                        float4 b = *(const float4*)(fin + ii.y + co);
                        float4 c = *(const float4*)(fin + ii.z + co);
                        float4 d = *(const float4*)(fin + ii.w + co);
                        r.x = wt.x*a.x + wt.y*b.x + wt.z*c.x + wt.w*d.x;
                        r.y = wt.x*a.y + wt.y*b.y + wt.z*c.y + wt.w*d.y;
                        r.z = wt.x*a.z + wt.y*b.z + wt.z*c.z + wt.w*d.z;
                        r.w = wt.x*a.w + wt.y*b.w + wt.z*c.w + wt.w*d.w;
                    } else {
                        int base = ((const int*)(smem + SIDX))[p];
                        r = make_float4(0.f, 0.f, 0.f, 0.f);
                        if (base >= 0) r = *(const float4*)(fin + base + co);
                    }
                    __nv_bfloat16 h0 = __float2bfloat16_rn(r.x);
                    __nv_bfloat16 h1 = __float2bfloat16_rn(r.y);
                    __nv_bfloat16 h2 = __float2bfloat16_rn(r.z);
                    __nv_bfloat16 h3 = __float2bfloat16_rn(r.w);
                    __nv_bfloat16 l0 = __float2bfloat16_rn(r.x - __bfloat162float(h0));
                    __nv_bfloat16 l1 = __float2bfloat16_rn(r.y - __bfloat162float(h1));
                    __nv_bfloat16 l2 = __float2bfloat16_rn(r.z - __bfloat162float(h2));
                    __nv_bfloat16 l3 = __float2bfloat16_rn(r.w - __bfloat162float(h3));
                    uint2 hp, lp;
                    hp.x = (uint32_t)__bfloat16_as_ushort(h0) | ((uint32_t)__bfloat16_as_ushort(h1) << 16);
                    hp.y = (uint32_t)__bfloat16_as_ushort(h2) | ((uint32_t)__bfloat16_as_ushort(h3) << 16);
                    lp.x = (uint32_t)__bfloat16_as_ushort(l0) | ((uint32_t)__bfloat16_as_ushort(l1) << 16);
                    lp.y = (uint32_t)__bfloat16_as_ushort(l2) | ((uint32_t)__bfloat16_as_ushort(l3) << 16);
                    uint32_t o  = (uint32_t)(p * 128 + (lid & 15) * 8);
                    uint32_t so = o ^ ((o >> 3) & 0x70);
                    *(uint2*)(ah + so) = hp;
                    *(uint2*)(al + so) = lp;
                }
            }
            asm volatile("fence.proxy.async.shared::cta;" ::: "memory");
            __syncthreads();

            if (tid == 0) {
                asm volatile("tcgen05.fence::after_thread_sync;" ::: "memory");
                const uint64_t DB =
                    (2ull << 61) | (1ull << 46) | (64ull << 32) | (1ull << 16);
                uint64_t adh = DB | (((sb + ABASE + (buf * 2 + 0) * 16384) >> 4) & 0x3FFF);
                uint64_t adl = DB | (((sb + ABASE + (buf * 2 + 1) * 16384) >> 4) & 0x3FFF);
                uint64_t bdh = DB | (((sb + BBASE + (buf * 2 + 0) * NB) >> 4) & 0x3FFF);
                uint64_t bdl = DB | (((sb + BBASE + (buf * 2 + 1) * NB) >> 4) & 0x3FFF);
#pragma unroll
                for (int k4 = 0; k4 < 4; k4++)
                    mma_f16_ss(tb, adh + 2 * k4, bdh + 2 * k4, IDESC, (ks | k4) != 0);
#pragma unroll
                for (int k4 = 0; k4 < 4; k4++)
                    mma_f16_ss(tb, adh + 2 * k4, bdl + 2 * k4, IDESC, 1);
#pragma unroll
                for (int k4 = 0; k4 < 4; k4++)
                    mma_f16_ss(tb, adl + 2 * k4, bdh + 2 * k4, IDESC, 1);
                tc_commit(sb + MBAR + 8 * buf);
            }
            u++;
        }
    }

    if (use0 > 0) mbar_wait(sb + MBAR + 0, (use0 - 1) & 1);
    if (use1 > 0) mbar_wait(sb + MBAR + 8, (use1 - 1) & 1);
    asm volatile("tcgen05.fence::after_thread_sync;" ::: "memory");

    if (tid < 128) {
        int m = bm0 + wid * 32 + lid;
        if (DEFORM) {
#pragma unroll
            for (int nb = 0; nb < 8; nb++) {
                uint32_t r[32];
                LDTM_X32(r, tb + nb * 32);
                asm volatile("tcgen05.wait::ld.sync.aligned;" ::: "memory");
                float4* dst = (float4*)(fout + (size_t)m * 256 + nb * 32);
#pragma unroll
                for (int q = 0; q < 8; q++)
                    dst[q] = make_float4(__uint_as_float(r[q*4+0]), __uint_as_float(r[q*4+1]),
                                         __uint_as_float(r[q*4+2]), __uint_as_float(r[q*4+3]));
            }
        } else {
            uint32_t r[32];
            LDTM_X32(r, tb);
            asm volatile("tcgen05.wait::ld.sync.aligned;" ::: "memory");
            if (finalOut) {
                int b = m >> 12, hw = m & 4095;
#pragma unroll
                for (int j = 0; j < 18; j++)
                    finalOut[((size_t)(b * 18 + j)) * HW_ + hw] = __uint_as_float(r[j]);
            } else {
                float4* dst = (float4*)(g_offraw + (size_t)m * 32);
#pragma unroll
                for (int q = 0; q < 8; q++)
                    dst[q] = make_float4(__uint_as_float(r[q*4+0]), __uint_as_float(r[q*4+1]),
                                         __uint_as_float(r[q*4+2]), __uint_as_float(r[q*4+3]));
            }
        }
    }
    __syncthreads();
    if (wid == 0) {
        asm volatile("tcgen05.dealloc.cta_group::1.sync.aligned.b32 %0, %1;"
                     :: "r"(tb), "r"((uint32_t)TMEMC));
    }
#endif  // HAS_TC
}

// ================= fallback FFMA GEMM (non-'a' targets only) ================
template <int BM, int BN, int TM, int TN, bool DEFORM>
__global__ __launch_bounds__(256, 2)
void gemmF_kernel(int fsel, int wsel, float* __restrict__ finalOut)
{
#if !HAS_TC
    constexpr int BK  = 16;
    constexpr int CPP = 256 / BM;
    constexpr int CH  = BK / CPP;
    constexpr int NW  = DEFORM ? 256 : 32;

    const float* __restrict__ fin = fsel ? g_feat1 : g_feat0;
    float* __restrict__ fout      = fsel ? g_feat0 : g_feat1;
    const float* __restrict__ wT  = DEFORM ? (g_wDt + (size_t)wsel * 9 * C_ * C_)
                                           : (g_wOt + (size_t)wsel * 9 * C_ * 32);

    __shared__ float  As[BK][BM + 4];
    __shared__ float  Bs[BK][BN];
    __shared__ int4   sIdx[BM];
    __shared__ float4 sW[BM];
    __shared__ int    sBase[BM];

    const int tid = threadIdx.x;
    const int bm0 = blockIdx.y * BM;
    const int bn0 = blockIdx.x * BN;
    const int ty = tid / (BN / TN);
    const int tx = tid % (BN / TN);
    const int p  = tid / CPP;
    const int cb = (tid % CPP) * CH;

    float acc[TM][TN];
#pragma unroll
    for (int i = 0; i < TM; i++)
#pragma unroll
        for (int j = 0; j < TN; j++) acc[i][j] = 0.f;

    for (int tap = 0; tap < 9; ++tap) {
        if (tid < BM) {
            int m = bm0 + tid;
            if (DEFORM) {
                sIdx[tid] = g_recIdx[(size_t)m * 9 + tap];
                sW[tid]   = g_recW[(size_t)m * 9 + tap];
            } else {
                int b = m >> 12, hw = m & 4095, h = hw >> 6, w = hw & 63;
                int yy = h + tap / 3 - 1, xx = w + tap % 3 - 1;
                sBase[tid] = (yy >= 0 && yy < H_ && xx >= 0 && xx < W_)
                             ? (((b << 12) + (yy << 6) + xx) << 8) : -1;
            }
        }
        for (int cc = 0; cc < C_; cc += BK) {
            __syncthreads();
            const float* wrow = wT + (size_t)(tap * C_ + cc) * NW + bn0;
            for (int q = tid; q < BK * BN / 4; q += 256) {
                int kk = q / (BN / 4), c4 = q % (BN / 4);
                *(float4*)&Bs[kk][c4 * 4] = *(const float4*)(wrow + (size_t)kk * NW + c4 * 4);
            }
            if (DEFORM) {
                int4 ii = sIdx[p]; float4 wwt = sW[p];
#pragma unroll
                for (int j4 = 0; j4 < CH / 4; j4++) {
                    int co = cc + cb + j4 * 4;
                    float4 a = *(const float4*)(fin + ii.x + co);
                    float4 b = *(const float4*)(fin + ii.y + co);
                    float4 c = *(const float4*)(fin + ii.z + co);
                    float4 d = *(const float4*)(fin + ii.w + co);
                    As[cb + j4*4 + 0][p] = wwt.x*a.x + wwt.y*b.x + wwt.z*c.x + wwt.w*d.x;
                    As[cb + j4*4 + 1][p] = wwt.x*a.y + wwt.y*b.y + wwt.z*c.y + wwt.w*d.y;
                    As[cb + j4*4 + 2][p] = wwt.x*a.z + wwt.y*b.z + wwt.z*c.z + wwt.w*d.z;
                    As[cb + j4*4 + 3][p] = wwt.x*a.w + wwt.y*b.w + wwt.z*c.w + wwt.w*d.w;
                }
            } else {
                int base = sBase[p];
#pragma unroll
                for (int j4 = 0; j4 < CH / 4; j4++) {
                    float4 r = make_float4(0.f, 0.f, 0.f, 0.f);
                    if (base >= 0) r = *(const float4*)(fin + base + cc + cb + j4 * 4);
                    As[cb + j4*4 + 0][p] = r.x; As[cb + j4*4 + 1][p] = r.y;
                    As[cb + j4*4 + 2][p] = r.z; As[cb + j4*4 + 3][p] = r.w;
                }
            }
            __syncthreads();
#pragma unroll
            for (int kk = 0; kk < BK; kk++) {
                float ra[TM], rb[TN];
#pragma unroll
                for (int i = 0; i < TM; i++) ra[i] = As[kk][ty * TM + i];
#pragma unroll
                for (int j = 0; j < TN; j++) rb[j] = Bs[kk][tx * TN + j];
#pragma unroll
                for (int i = 0; i < TM; i++)
#pragma unroll
                    for (int j = 0; j < TN; j++) acc[i][j] += ra[i] * rb[j];
            }
        }
    }

    if (DEFORM) {
#pragma unroll
        for (int i = 0; i < TM; i++) {
            int m = bm0 + ty * TM + i;
            float* o = fout + (size_t)m * C_ + bn0 + tx * TN;
#pragma unroll
            for (int j4 = 0; j4 < TN / 4; j4++)
                *(float4*)(o + j4 * 4) = make_float4(acc[i][j4*4+0], acc[i][j4*4+1],
                                                     acc[i][j4*4+2], acc[i][j4*4+3]);
        }
    } else if (finalOut == nullptr) {
#pragma unroll
        for (int i = 0; i < TM; i++) {
            int m = bm0 + ty * TM + i;
#pragma unroll
            for (int j = 0; j < TN; j++)
                g_offraw[(size_t)m * 32 + tx * TN + j] = acc[i][j];
        }
    } else {
#pragma unroll
        for (int i = 0; i < TM; i++) {
            int m = bm0 + ty * TM + i;
            int b = m >> 12, hw = m & 4095;
#pragma unroll
            for (int j = 0; j < TN; j++) {
                int n = tx * TN + j;
                if (n < 18) finalOut[((size_t)(b * 18 + n)) * HW_ + hw] = acc[i][j];
            }
        }
    }
#endif  // !HAS_TC
}

// ---------------------------------------------------------------------------
extern "C" void kernel_launch(void* const* d_in, const int* in_sizes, int n_in,
                              void* d_out, int out_size)
{
    (void)in_sizes; (void)n_in; (void)out_size;
    const float* x  = (const float*)d_in[0];
    const float* y  = (const float*)d_in[1];
    const float* oW = (const float*)d_in[2];
    const float* dW = (const float*)d_in[3];
    float* out = (float*)d_out;

    const int SMEM_D = 73728 + 4 * (256 * 128);  // 204800
    const int SMEM_O = 73728 + 4 * (32 * 128);   // 90112
    cudaFuncSetAttribute(conv_kernel<true>,  cudaFuncAttributeMaxDynamicSharedMemorySize, SMEM_D);
    cudaFuncSetAttribute(conv_kernel<false>, cudaFuncAttributeMaxDynamicSharedMemorySize, SMEM_O);

    dim3 pb(32, 8), pg(HW_ / 32, C_ / 32, B_);
    pack_kernel<<<pg, pb>>>(x, y);

    const int G = 3 * 9 * 4 * 2048 + 4 * 9 * 4 * 256;
    wsplit_kernel<<<(G + 255) / 256, 256>>>(oW, dW);
    const int T = 4 * 9 * C_ * 32 + 3 * 9 * C_ * C_;
    wtrans_kernel<<<(T + 255) / 256, 256>>>(oW, dW);

    dim3 gOffF(1, M_ / 64);
    dim3 gDefF(C_ / 128, M_ / 128);

    int fsel = 0;
    for (int it = 0; it < 3; ++it) {
        conv_kernel<false><<<128, 256, SMEM_O>>>(fsel, it, nullptr);
        gemmF_kernel<64, 32, 4, 2, false><<<gOffF, 256>>>(fsel, it, nullptr);
        coords_kernel<<<(M_ * 9 + 255) / 256, 256>>>();
        conv_kernel<true><<<128, 256, SMEM_D>>>(fsel, it, nullptr);
        gemmF_kernel<128, 128, 8, 8, true><<<gDefF, 256>>>(fsel, it, nullptr);
        fsel ^= 1;
    }
    conv_kernel<false><<<128, 256, SMEM_O>>>(fsel, 3, out);
    gemmF_kernel<64, 32, 4, 2, false><<<gOffF, 256>>>(fsel, 3, out);
}

// round 6
// speedup vs baseline: 3.1384x; 1.1488x over previous
#include <cuda_runtime.h>
#include <cuda_bf16.h>
#include <cstdint>

#if defined(__CUDA_ARCH__) && (defined(__CUDA_ARCH_FEAT_SM103_ALL) || defined(__CUDA_ARCH_SPECIFIC__) || defined(__CUDA_ARCH_FAMILY_SPECIFIC__))
#define HAS_TC 1
#else
#define HAS_TC 0
#endif

static constexpr int B_  = 4;
static constexpr int H_  = 64;
static constexpr int W_  = 64;
static constexpr int C_  = 256;
static constexpr int HW_ = H_ * W_;   // 4096
static constexpr int M_  = B_ * HW_;  // 16384

// ---------------- device scratch -------------------------------------------
__device__ float  g_feat0[(size_t)M_ * C_];
__device__ float  g_feat1[(size_t)M_ * C_];
__device__ int4   g_recIdx[(size_t)M_ * 9];
__device__ float4 g_recW[(size_t)M_ * 9];
__device__ __nv_bfloat16 g_wDs[(size_t)3 * 9 * 4 * 2 * 256 * 64];
__device__ __nv_bfloat16 g_wOs[(size_t)4 * 9 * 4 * 2 * 32 * 64];

// ---------------- PTX helpers ----------------------------------------------
__device__ __forceinline__ uint32_t smem_u32(const void* p) {
    uint32_t a;
    asm("{ .reg .u64 t; cvta.to.shared.u64 t, %1; cvt.u32.u64 %0, t; }" : "=r"(a) : "l"(p));
    return a;
}
#if HAS_TC
__device__ __forceinline__ void mbar_init(uint32_t a, uint32_t cnt) {
    asm volatile("mbarrier.init.shared.b64 [%0], %1;" :: "r"(a), "r"(cnt) : "memory");
}
__device__ __forceinline__ void mbar_wait(uint32_t a, uint32_t phase) {
    asm volatile(
        "{\n\t.reg .pred P;\n\t"
        "WL_%=:\n\t"
        "mbarrier.try_wait.parity.acquire.cta.shared::cta.b64 P, [%0], %1, 0x989680;\n\t"
        "@P bra.uni WD_%=;\n\t"
        "bra.uni WL_%=;\n\t"
        "WD_%=:\n\t}"
        :: "r"(a), "r"(phase) : "memory");
}
__device__ __forceinline__ void tc_commit(uint32_t mbar) {
    asm volatile(
        "tcgen05.commit.cta_group::1.mbarrier::arrive::one.shared::cluster.b64 [%0];"
        :: "r"(mbar) : "memory");
}
__device__ __forceinline__ void mma_f16_ss(uint32_t d, uint64_t ad, uint64_t bd,
                                           uint32_t idesc, uint32_t en) {
    asm volatile(
        "{\n\t.reg .pred p;\n\t"
        "setp.ne.u32 p, %4, 0;\n\t"
        "tcgen05.mma.cta_group::1.kind::f16 [%0], %1, %2, %3, {%5,%5,%5,%5}, p;\n\t}"
        :: "r"(d), "l"(ad), "l"(bd), "r"(idesc), "r"(en), "r"(0u) : "memory");
}
// split pair (a,b) into packed bf16 hi-pair and lo-pair
__device__ __forceinline__ void split2(float a, float b, uint32_t& hp, uint32_t& lp) {
    asm("cvt.rn.bf16x2.f32 %0, %1, %2;" : "=r"(hp) : "f"(b), "f"(a));
    float fa = __uint_as_float(hp << 16);
    float fb = __uint_as_float(hp & 0xFFFF0000u);
    float la = a - fa, lb = b - fb;
    asm("cvt.rn.bf16x2.f32 %0, %1, %2;" : "=r"(lp) : "f"(lb), "f"(la));
}
#define LDTM_X32(r, addr) \
    asm volatile( \
        "tcgen05.ld.sync.aligned.32x32b.x32.b32 " \
        "{%0,%1,%2,%3,%4,%5,%6,%7,%8,%9,%10,%11,%12,%13,%14,%15," \
        "%16,%17,%18,%19,%20,%21,%22,%23,%24,%25,%26,%27,%28,%29,%30,%31}, [%32];" \
        : "=r"((r)[0]),"=r"((r)[1]),"=r"((r)[2]),"=r"((r)[3]), \
          "=r"((r)[4]),"=r"((r)[5]),"=r"((r)[6]),"=r"((r)[7]), \
          "=r"((r)[8]),"=r"((r)[9]),"=r"((r)[10]),"=r"((r)[11]), \
          "=r"((r)[12]),"=r"((r)[13]),"=r"((r)[14]),"=r"((r)[15]), \
          "=r"((r)[16]),"=r"((r)[17]),"=r"((r)[18]),"=r"((r)[19]), \
          "=r"((r)[20]),"=r"((r)[21]),"=r"((r)[22]),"=r"((r)[23]), \
          "=r"((r)[24]),"=r"((r)[25]),"=r"((r)[26]),"=r"((r)[27]), \
          "=r"((r)[28]),"=r"((r)[29]),"=r"((r)[30]),"=r"((r)[31]) \
        : "r"(addr))
#endif

// ---------------- pack: NCHW x,y -> NHWC concat feat0 ----------------------
__global__ void pack_kernel(const float* __restrict__ x, const float* __restrict__ y)
{
    __shared__ float t[32][33];
    int b = blockIdx.z, hw0 = blockIdx.x * 32, c0 = blockIdx.y * 32;
    int tx = threadIdx.x, ty = threadIdx.y;
#pragma unroll
    for (int i = 0; i < 32; i += 8) {
        int c = c0 + ty + i;
        const float* s = (c < 128) ? (x + ((size_t)b * 128 + c) * HW_)
                                   : (y + ((size_t)b * 128 + (c - 128)) * HW_);
        t[ty + i][tx] = s[hw0 + tx];
    }
    __syncthreads();
#pragma unroll
    for (int i = 0; i < 32; i += 8)
        g_feat0[((size_t)b * HW_ + hw0 + ty + i) * C_ + c0 + tx] = t[tx][ty + i];
}

// ---------------- weight split + pre-swizzle --------------------------------
__global__ void wsplit_kernel(const float* __restrict__ oW, const float* __restrict__ dW)
{
#if HAS_TC
    const int GD = 3 * 9 * 4 * 2048;
    const int GO = 4 * 9 * 4 * 256;
    int g = blockIdx.x * blockDim.x + threadIdx.x;
    if (g >= GD + GO) return;
    if (g < GD) {
        int t = g >> 11, o = g & 2047;
        int chunk = t & 3, tap = (t >> 2) % 9, it = (t >> 2) / 9;
        uint32_t boff = (uint32_t)o * 16;
        uint32_t un = boff ^ ((boff >> 3) & 0x70);
        int n = un >> 7, k0 = (un & 127) >> 1;
        uint32_t hp[4], lp[4];
#pragma unroll
        for (int j2 = 0; j2 < 4; j2++) {
            float v0 = dW[((size_t)(it * 256 + n) * 256 + (size_t)(chunk * 64 + k0 + j2 * 2)) * 9 + tap];
            float v1 = dW[((size_t)(it * 256 + n) * 256 + (size_t)(chunk * 64 + k0 + j2 * 2 + 1)) * 9 + tap];
            split2(v0, v1, hp[j2], lp[j2]);
        }
        char* base = (char*)(g_wDs + (size_t)(((it * 9 + tap) * 4 + chunk) * 2) * 16384);
        *(uint4*)(base + boff)         = make_uint4(hp[0], hp[1], hp[2], hp[3]);
        *(uint4*)(base + 32768 + boff) = make_uint4(lp[0], lp[1], lp[2], lp[3]);
    } else {
        int g2 = g - GD;
        int t = g2 >> 8, o = g2 & 255;
        int chunk = t & 3, tap = (t >> 2) % 9, it = (t >> 2) / 9;
        uint32_t boff = (uint32_t)o * 16;
        uint32_t un = boff ^ ((boff >> 3) & 0x70);
        int n = un >> 7, k0 = (un & 127) >> 1;
        uint32_t hp[4], lp[4];
#pragma unroll
        for (int j2 = 0; j2 < 4; j2++) {
            float v0 = (n < 18) ? oW[((size_t)(it * 18 + n) * 256 + (size_t)(chunk * 64 + k0 + j2 * 2)) * 9 + tap] : 0.f;
            float v1 = (n < 18) ? oW[((size_t)(it * 18 + n) * 256 + (size_t)(chunk * 64 + k0 + j2 * 2 + 1)) * 9 + tap] : 0.f;
            split2(v0, v1, hp[j2], lp[j2]);
        }
        char* base = (char*)(g_wOs + (size_t)(((it * 9 + tap) * 4 + chunk) * 2) * 2048);
        *(uint4*)(base + boff)        = make_uint4(hp[0], hp[1], hp[2], hp[3]);
        *(uint4*)(base + 4096 + boff) = make_uint4(lp[0], lp[1], lp[2], lp[3]);
    }
#endif
}

#if HAS_TC
// shared coords math: offsets (dy,dx) for pixel m, tap k -> gather record
__device__ __forceinline__ void make_record(int m, int k, float dy, float dx)
{
    int b = m >> 12, hw = m & 4095, h = hw >> 6, w = hw & 63;
    float py = dy + (float)(k / 3 - 1) + (float)h;
    float px = dx + (float)(k % 3 - 1) + (float)w;
    float y0f = floorf(py), x0f = floorf(px);
    float wy1 = py - y0f, wy0 = 1.f - wy1;
    float wx1 = px - x0f, wx0 = 1.f - wx1;
    int y0 = (int)y0f, x0 = (int)x0f, y1 = y0 + 1, x1 = x0 + 1;
    int4 ii; float4 ww;
    {
        bool v = (y0 >= 0 && y0 < H_ && x0 >= 0 && x0 < W_);
        int yc = min(max(y0,0),H_-1), xc = min(max(x0,0),W_-1);
        ii.x = ((b << 12) + (yc << 6) + xc) << 8;  ww.x = v ? wy0 * wx0 : 0.f;
    }
    {
        bool v = (y0 >= 0 && y0 < H_ && x1 >= 0 && x1 < W_);
        int yc = min(max(y0,0),H_-1), xc = min(max(x1,0),W_-1);
        ii.y = ((b << 12) + (yc << 6) + xc) << 8;  ww.y = v ? wy0 * wx1 : 0.f;
    }
    {
        bool v = (y1 >= 0 && y1 < H_ && x0 >= 0 && x0 < W_);
        int yc = min(max(y1,0),H_-1), xc = min(max(x0,0),W_-1);
        ii.z = ((b << 12) + (yc << 6) + xc) << 8;  ww.z = v ? wy1 * wx0 : 0.f;
    }
    {
        bool v = (y1 >= 0 && y1 < H_ && x1 >= 0 && x1 < W_);
        int yc = min(max(y1,0),H_-1), xc = min(max(x1,0),W_-1);
        ii.w = ((b << 12) + (yc << 6) + xc) << 8;  ww.w = v ? wy1 * wx1 : 0.f;
    }
    g_recIdx[(size_t)m * 9 + k] = ii;
    g_recW[(size_t)m * 9 + k]   = ww;
}
#endif

// ================= offset conv (N=32), 4-deep pipeline, fused coords =======
__global__ __launch_bounds__(256)
void offconv_kernel(int fsel, int wsel, float* __restrict__ finalOut)
{
#if HAS_TC
    constexpr int NB = 32 * 128;   // 4 KB per split
    constexpr uint32_t IDESC =
        (1u << 4) | (1u << 7) | (1u << 10) | (4u << 17) | (8u << 24);

    extern __shared__ char smem[];
    const uint32_t sb = smem_u32(smem);
    const int TMEMP = 0, MBAR = 16, SIDX = 64;
    const int ABASE = 8192;                 // 4 stages x 2 splits x 16KB
    const int BBASE = 8192 + 131072;        // 4 stages x 2 splits x 4KB

    const float* __restrict__ fin = fsel ? g_feat1 : g_feat0;
    const __nv_bfloat16* __restrict__ wsrc = g_wOs + (size_t)wsel * 9 * 4 * 2 * 2048;

    const int tid = threadIdx.x, wid = tid >> 5, lid = tid & 31;
    const int bm0 = blockIdx.x * 128;

    if (wid == 0) {
        asm volatile("tcgen05.alloc.cta_group::1.sync.aligned.shared::cta.b32 [%0], %1;"
                     :: "r"(sb + TMEMP), "r"(128u) : "memory");
        asm volatile("tcgen05.relinquish_alloc_permit.cta_group::1.sync.aligned;");
    }
    if (tid < 4) mbar_init(sb + MBAR + 8 * tid, 1);
    // preload all 9 taps' base indices
    for (int t = tid; t < 9 * 128; t += 256) {
        int tap = t >> 7, p = t & 127;
        int m = bm0 + p;
        int b = m >> 12, hw = m & 4095, h = hw >> 6, w = hw & 63;
        int yy = h + tap / 3 - 1, xx = w + tap % 3 - 1;
        ((int*)(smem + SIDX))[t] =
            (yy >= 0 && yy < H_ && xx >= 0 && xx < W_)
                ? (((b << 12) + (yy << 6) + xx) << 8) : -1;
    }
    __syncthreads();
    uint32_t tb;
    asm volatile("ld.shared.b32 %0, [%1];" : "=r"(tb) : "r"(sb + TMEMP));

    const int cl4 = (lid & 15) * 4;
    const int ph  = (lid >> 4);

    for (int ks = 0; ks < 36; ++ks) {
        const int tap = ks >> 2, ch = ks & 3;
        const int buf = ks & 3;
        const int uses = ks >> 2;
        if (uses > 0) mbar_wait(sb + MBAR + 8 * buf, (uses - 1) & 1);

        // B tile (1 float4 per thread per split)
        {
            const char* bsh = (const char*)(wsrc + (size_t)(ks * 2) * 2048);
            ((float4*)(smem + BBASE + (buf * 2 + 0) * NB))[tid] = ((const float4*)bsh)[tid];
            ((float4*)(smem + BBASE + (buf * 2 + 1) * NB))[tid] = ((const float4*)(bsh + NB))[tid];
        }
        // A tile
        {
            char* ah = smem + ABASE + (buf * 2 + 0) * 16384;
            char* al = smem + ABASE + (buf * 2 + 1) * 16384;
            const int co = ch * 64 + cl4;
            const int* sidx = (const int*)(smem + SIDX) + tap * 128;
#pragma unroll
            for (int pass = 0; pass < 8; ++pass) {
                int p = pass * 16 + wid * 2 + ph;
                int base = sidx[p];
                float4 r = make_float4(0.f, 0.f, 0.f, 0.f);
                if (base >= 0) r = *(const float4*)(fin + base + co);
                uint2 hp, lp;
                split2(r.x, r.y, hp.x, lp.x);
                split2(r.z, r.w, hp.y, lp.y);
                uint32_t o  = (uint32_t)(p * 128 + (lid & 15) * 8);
                uint32_t so = o ^ ((o >> 3) & 0x70);
                *(uint2*)(ah + so) = hp;
                *(uint2*)(al + so) = lp;
            }
        }
        asm volatile("fence.proxy.async.shared::cta;" ::: "memory");
        __syncthreads();

        if (tid == 0) {
            asm volatile("tcgen05.fence::after_thread_sync;" ::: "memory");
            const uint64_t DB = (2ull << 61) | (1ull << 46) | (64ull << 32) | (1ull << 16);
            uint64_t adh = DB | (((sb + ABASE + (buf * 2 + 0) * 16384) >> 4) & 0x3FFF);
            uint64_t adl = DB | (((sb + ABASE + (buf * 2 + 1) * 16384) >> 4) & 0x3FFF);
            uint64_t bdh = DB | (((sb + BBASE + (buf * 2 + 0) * NB) >> 4) & 0x3FFF);
            uint64_t bdl = DB | (((sb + BBASE + (buf * 2 + 1) * NB) >> 4) & 0x3FFF);
#pragma unroll
            for (int k4 = 0; k4 < 4; k4++)
                mma_f16_ss(tb, adh + 2 * k4, bdh + 2 * k4, IDESC, (ks | k4) != 0);
#pragma unroll
            for (int k4 = 0; k4 < 4; k4++)
                mma_f16_ss(tb, adh + 2 * k4, bdl + 2 * k4, IDESC, 1);
#pragma unroll
            for (int k4 = 0; k4 < 4; k4++)
                mma_f16_ss(tb, adl + 2 * k4, bdh + 2 * k4, IDESC, 1);
            tc_commit(sb + MBAR + 8 * buf);
        }
    }

    // last commit (ks=35, buf=3, 9th completion -> parity 0) implies all done
    mbar_wait(sb + MBAR + 8 * 3, 0);
    asm volatile("tcgen05.fence::after_thread_sync;" ::: "memory");

    if (tid < 128) {
        int m = bm0 + wid * 32 + lid;
        uint32_t r[32];
        LDTM_X32(r, tb);
        asm volatile("tcgen05.wait::ld.sync.aligned;" ::: "memory");
        if (finalOut) {
            int b = m >> 12, hw = m & 4095;
#pragma unroll
            for (int j = 0; j < 18; j++)
                finalOut[((size_t)(b * 18 + j)) * HW_ + hw] = __uint_as_float(r[j]);
        } else {
#pragma unroll
            for (int k = 0; k < 9; k++)
                make_record(m, k, __uint_as_float(r[2 * k]), __uint_as_float(r[2 * k + 1]));
        }
    }
    __syncthreads();
    if (wid == 0)
        asm volatile("tcgen05.dealloc.cta_group::1.sync.aligned.b32 %0, %1;"
                     :: "r"(tb), "r"(128u));
#endif
}

// ================= deform conv (N=256), 2-deep pipeline =====================
__global__ __launch_bounds__(256)
void defconv_kernel(int fsel, int wsel)
{
#if HAS_TC
    constexpr int NB = 256 * 128;   // 32 KB per split
    constexpr uint32_t IDESC =
        (1u << 4) | (1u << 7) | (1u << 10) | (32u << 17) | (8u << 24);

    extern __shared__ char smem[];
    const uint32_t sb = smem_u32(smem);
    const int TMEMP = 0, MBAR = 16, SIDX = 64, SWT = 64 + 2048;
    const int ABASE = 8192;          // 2 stages x 2 splits x 16KB = 64KB
    const int BBASE = 8192 + 65536;  // 2 stages x 2 splits x 32KB = 128KB

    const float* __restrict__ fin = fsel ? g_feat1 : g_feat0;
    float* __restrict__ fout      = fsel ? g_feat0 : g_feat1;
    const __nv_bfloat16* __restrict__ wsrc = g_wDs + (size_t)wsel * 9 * 4 * 2 * 16384;

    const int tid = threadIdx.x, wid = tid >> 5, lid = tid & 31;
    const int bm0 = blockIdx.x * 128;

    if (wid == 0) {
        asm volatile("tcgen05.alloc.cta_group::1.sync.aligned.shared::cta.b32 [%0], %1;"
                     :: "r"(sb + TMEMP), "r"(512u) : "memory");
        asm volatile("tcgen05.relinquish_alloc_permit.cta_group::1.sync.aligned;");
    }
    if (tid < 2) mbar_init(sb + MBAR + 8 * tid, 1);
    __syncthreads();
    uint32_t tb;
    asm volatile("ld.shared.b32 %0, [%1];" : "=r"(tb) : "r"(sb + TMEMP));

    int use0 = 0, use1 = 0;
    const int cl4 = (lid & 15) * 4;
    const int ph  = (lid >> 4);

    for (int tap = 0; tap < 9; ++tap) {
        if (tid < 128) {
            int m = bm0 + tid;
            ((int4*)(smem + SIDX))[tid]  = g_recIdx[(size_t)m * 9 + tap];
            ((float4*)(smem + SWT))[tid] = g_recW[(size_t)m * 9 + tap];
        }
        __syncthreads();

        for (int ch = 0; ch < 4; ++ch) {
            const int ks = tap * 4 + ch;
            const int buf = ks & 1;
            int& u = buf ? use1 : use0;
            if (u > 0) mbar_wait(sb + MBAR + 8 * buf, (u - 1) & 1);

            {
                const char* bsh = (const char*)(wsrc + (size_t)(ks * 2) * 16384);
                float4* dh = (float4*)(smem + BBASE + (buf * 2 + 0) * NB);
                float4* dl = (float4*)(smem + BBASE + (buf * 2 + 1) * NB);
                const float4* sh = (const float4*)bsh;
                const float4* sl = (const float4*)(bsh + NB);
#pragma unroll
                for (int q0 = 0; q0 < NB / 16; q0 += 256) {
                    dh[q0 + tid] = sh[q0 + tid];
                    dl[q0 + tid] = sl[q0 + tid];
                }
            }
            {
                char* ah = smem + ABASE + (buf * 2 + 0) * 16384;
                char* al = smem + ABASE + (buf * 2 + 1) * 16384;
                const int co = ch * 64 + cl4;
#pragma unroll
                for (int pass = 0; pass < 8; ++pass) {
                    int p = pass * 16 + wid * 2 + ph;
                    int4   ii = ((const int4*)(smem + SIDX))[p];
                    float4 wt = ((const float4*)(smem + SWT))[p];
                    float4 a = *(const float4*)(fin + ii.x + co);
                    float4 b = *(const float4*)(fin + ii.y + co);
                    float4 c = *(const float4*)(fin + ii.z + co);
                    float4 d = *(const float4*)(fin + ii.w + co);
                    float4 r;
                    r.x = wt.x*a.x + wt.y*b.x + wt.z*c.x + wt.w*d.x;
                    r.y = wt.x*a.y + wt.y*b.y + wt.z*c.y + wt.w*d.y;
                    r.z = wt.x*a.z + wt.y*b.z + wt.z*c.z + wt.w*d.z;
                    r.w = wt.x*a.w + wt.y*b.w + wt.z*c.w + wt.w*d.w;
                    uint2 hp, lp;
                    split2(r.x, r.y, hp.x, lp.x);
                    split2(r.z, r.w, hp.y, lp.y);
                    uint32_t o  = (uint32_t)(p * 128 + (lid & 15) * 8);
                    uint32_t so = o ^ ((o >> 3) & 0x70);
                    *(uint2*)(ah + so) = hp;
                    *(uint2*)(al + so) = lp;
                }
            }
            asm volatile("fence.proxy.async.shared::cta;" ::: "memory");
            __syncthreads();

            if (tid == 0) {
                asm volatile("tcgen05.fence::after_thread_sync;" ::: "memory");
                const uint64_t DB = (2ull << 61) | (1ull << 46) | (64ull << 32) | (1ull << 16);
                uint64_t adh = DB | (((sb + ABASE + (buf * 2 + 0) * 16384) >> 4) & 0x3FFF);
                uint64_t adl = DB | (((sb + ABASE + (buf * 2 + 1) * 16384) >> 4) & 0x3FFF);
                uint64_t bdh = DB | (((sb + BBASE + (buf * 2 + 0) * NB) >> 4) & 0x3FFF);
                uint64_t bdl = DB | (((sb + BBASE + (buf * 2 + 1) * NB) >> 4) & 0x3FFF);
#pragma unroll
                for (int k4 = 0; k4 < 4; k4++)
                    mma_f16_ss(tb, adh + 2 * k4, bdh + 2 * k4, IDESC, (ks | k4) != 0);
#pragma unroll
                for (int k4 = 0; k4 < 4; k4++)
                    mma_f16_ss(tb, adh + 2 * k4, bdl + 2 * k4, IDESC, 1);
#pragma unroll
                for (int k4 = 0; k4 < 4; k4++)
                    mma_f16_ss(tb, adl + 2 * k4, bdh + 2 * k4, IDESC, 1);
                tc_commit(sb + MBAR + 8 * buf);
            }
            u++;
        }
    }

    // last commit on buf1 (18th completion -> parity 1) implies all done
    mbar_wait(sb + MBAR + 8, 1);
    asm volatile("tcgen05.fence::after_thread_sync;" ::: "memory");

    if (tid < 128) {
        int m = bm0 + wid * 32 + lid;
#pragma unroll
        for (int nb = 0; nb < 8; nb++) {
            uint32_t r[32];
            LDTM_X32(r, tb + nb * 32);
            asm volatile("tcgen05.wait::ld.sync.aligned;" ::: "memory");
            float4* dst = (float4*)(fout + (size_t)m * 256 + nb * 32);
#pragma unroll
            for (int q = 0; q < 8; q++)
                dst[q] = make_float4(__uint_as_float(r[q*4+0]), __uint_as_float(r[q*4+1]),
                                     __uint_as_float(r[q*4+2]), __uint_as_float(r[q*4+3]));
        }
    }
    __syncthreads();
    if (wid == 0)
        asm volatile("tcgen05.dealloc.cta_group::1.sync.aligned.b32 %0, %1;"
                     :: "r"(tb), "r"(512u));
#endif
}

// ---------------------------------------------------------------------------
extern "C" void kernel_launch(void* const* d_in, const int* in_sizes, int n_in,
                              void* d_out, int out_size)
{
    (void)in_sizes; (void)n_in; (void)out_size;
    const float* x  = (const float*)d_in[0];
    const float* y  = (const float*)d_in[1];
    const float* oW = (const float*)d_in[2];
    const float* dW = (const float*)d_in[3];
    float* out = (float*)d_out;

    const int SMEM_D = 8192 + 65536 + 131072;   // 204800
    const int SMEM_O = 8192 + 131072 + 32768;   // 172032
    cudaFuncSetAttribute(defconv_kernel, cudaFuncAttributeMaxDynamicSharedMemorySize, SMEM_D);
    cudaFuncSetAttribute(offconv_kernel, cudaFuncAttributeMaxDynamicSharedMemorySize, SMEM_O);

    dim3 pb(32, 8), pg(HW_ / 32, C_ / 32, B_);
    pack_kernel<<<pg, pb>>>(x, y);

    const int G = 3 * 9 * 4 * 2048 + 4 * 9 * 4 * 256;
    wsplit_kernel<<<(G + 255) / 256, 256>>>(oW, dW);

    int fsel = 0;
    for (int it = 0; it < 3; ++it) {
        offconv_kernel<<<128, 256, SMEM_O>>>(fsel, it, nullptr);
        defconv_kernel<<<128, 256, SMEM_D>>>(fsel, it);
        fsel ^= 1;
    }
    offconv_kernel<<<128, 256, SMEM_O>>>(fsel, 3, out);
}